// round 2
// baseline (speedup 1.0000x reference)
#include <cuda_runtime.h>
#include <stdint.h>

// 12-bit ripple-borrow subtractor on binary (0/1) float spikes.
// Boolean-exact collapse: diffs = bits of ((a-b) & 0xFFF) MSB-first,
// borrow = (a < b). Output: [B*12] diffs row-major, then [B] borrow.
//
// HBM-bound streaming kernel: 2 rows/thread, __ldcs/__stcs (evict-first),
// integer bit tests on raw words (0/1 floats: nonzero word == 1.0f).

__device__ __forceinline__ uint32_t pack12(const uint4& w0, const uint4& w1, const uint4& w2) {
    // index 0 = MSB (bit 11) ... index 11 = LSB (bit 0)
    uint32_t v = 0;
    v |= (w0.x ? 1u : 0u) << 11;
    v |= (w0.y ? 1u : 0u) << 10;
    v |= (w0.z ? 1u : 0u) << 9;
    v |= (w0.w ? 1u : 0u) << 8;
    v |= (w1.x ? 1u : 0u) << 7;
    v |= (w1.y ? 1u : 0u) << 6;
    v |= (w1.z ? 1u : 0u) << 5;
    v |= (w1.w ? 1u : 0u) << 4;
    v |= (w2.x ? 1u : 0u) << 3;
    v |= (w2.y ? 1u : 0u) << 2;
    v |= (w2.z ? 1u : 0u) << 1;
    v |= (w2.w ? 1u : 0u);
    return v;
}

__device__ __forceinline__ uint32_t bitf(uint32_t d, int bit) {
    // 1.0f (0x3F800000) if bit set else 0.0f
    return ((d >> bit) & 1u) * 0x3F800000u;
}

__global__ void __launch_bounds__(256) sub12_kernel(
    const uint4* __restrict__ A4,
    const uint4* __restrict__ B4,
    uint4* __restrict__ D4,
    float* __restrict__ Borrow,
    int batch)
{
    const int base = (blockIdx.x * blockDim.x + threadIdx.x) * 2;
    if (base >= batch) return;

#pragma unroll
    for (int r = 0; r < 2; r++) {
        const int i = base + r;
        const uint4 a0 = __ldcs(&A4[i * 3 + 0]);
        const uint4 a1 = __ldcs(&A4[i * 3 + 1]);
        const uint4 a2 = __ldcs(&A4[i * 3 + 2]);
        const uint4 b0 = __ldcs(&B4[i * 3 + 0]);
        const uint4 b1 = __ldcs(&B4[i * 3 + 1]);
        const uint4 b2 = __ldcs(&B4[i * 3 + 2]);

        const uint32_t ia = pack12(a0, a1, a2);
        const uint32_t ib = pack12(b0, b1, b2);
        const uint32_t d  = (ia - ib) & 0xFFFu;

        uint4 o0, o1, o2;
        o0.x = bitf(d, 11); o0.y = bitf(d, 10); o0.z = bitf(d, 9); o0.w = bitf(d, 8);
        o1.x = bitf(d, 7);  o1.y = bitf(d, 6);  o1.z = bitf(d, 5); o1.w = bitf(d, 4);
        o2.x = bitf(d, 3);  o2.y = bitf(d, 2);  o2.z = bitf(d, 1); o2.w = bitf(d, 0);

        __stcs(&D4[i * 3 + 0], o0);
        __stcs(&D4[i * 3 + 1], o1);
        __stcs(&D4[i * 3 + 2], o2);
        __stcs(&Borrow[i], __uint_as_float((ia < ib) ? 0x3F800000u : 0u));
    }
}

extern "C" void kernel_launch(void* const* d_in, const int* in_sizes, int n_in,
                              void* d_out, int out_size)
{
    const uint4* A4 = (const uint4*)d_in[0];
    const uint4* B4 = (const uint4*)d_in[1];
    const int batch = in_sizes[0] / 12;

    float* out = (float*)d_out;
    uint4* D4 = (uint4*)out;
    float* Borrow = out + (size_t)batch * 12;

    const int threads = 256;
    const int rows_per_block = threads * 2;
    const int blocks = (batch + rows_per_block - 1) / rows_per_block;
    sub12_kernel<<<blocks, threads>>>(A4, B4, D4, Borrow, batch);
}

// round 3
// speedup vs baseline: 1.0020x; 1.0020x over previous
#include <cuda_runtime.h>
#include <stdint.h>

// 12-bit ripple-borrow subtractor on binary (0/1) float spikes.
// Boolean-exact collapse: diffs = bits of ((a-b) & 0xFFF) MSB-first,
// borrow = (a < b). Output: [B*12] diffs row-major, then [B] borrow.
//
// HBM-bound streaming kernel: 2 rows/thread, __ldcs/__stcs (evict-first),
// integer bit tests on raw words (0/1 floats: nonzero word == 1.0f).

__device__ __forceinline__ uint32_t pack12(const uint4& w0, const uint4& w1, const uint4& w2) {
    // index 0 = MSB (bit 11) ... index 11 = LSB (bit 0)
    uint32_t v = 0;
    v |= (w0.x ? 1u : 0u) << 11;
    v |= (w0.y ? 1u : 0u) << 10;
    v |= (w0.z ? 1u : 0u) << 9;
    v |= (w0.w ? 1u : 0u) << 8;
    v |= (w1.x ? 1u : 0u) << 7;
    v |= (w1.y ? 1u : 0u) << 6;
    v |= (w1.z ? 1u : 0u) << 5;
    v |= (w1.w ? 1u : 0u) << 4;
    v |= (w2.x ? 1u : 0u) << 3;
    v |= (w2.y ? 1u : 0u) << 2;
    v |= (w2.z ? 1u : 0u) << 1;
    v |= (w2.w ? 1u : 0u);
    return v;
}

__device__ __forceinline__ uint32_t bitf(uint32_t d, int bit) {
    // 1.0f (0x3F800000) if bit set else 0.0f
    return ((d >> bit) & 1u) * 0x3F800000u;
}

__global__ void __launch_bounds__(256) sub12_kernel(
    const uint4* __restrict__ A4,
    const uint4* __restrict__ B4,
    uint4* __restrict__ D4,
    float* __restrict__ Borrow,
    int batch)
{
    const int base = (blockIdx.x * blockDim.x + threadIdx.x) * 2;
    if (base >= batch) return;

#pragma unroll
    for (int r = 0; r < 2; r++) {
        const int i = base + r;
        const uint4 a0 = __ldcs(&A4[i * 3 + 0]);
        const uint4 a1 = __ldcs(&A4[i * 3 + 1]);
        const uint4 a2 = __ldcs(&A4[i * 3 + 2]);
        const uint4 b0 = __ldcs(&B4[i * 3 + 0]);
        const uint4 b1 = __ldcs(&B4[i * 3 + 1]);
        const uint4 b2 = __ldcs(&B4[i * 3 + 2]);

        const uint32_t ia = pack12(a0, a1, a2);
        const uint32_t ib = pack12(b0, b1, b2);
        const uint32_t d  = (ia - ib) & 0xFFFu;

        uint4 o0, o1, o2;
        o0.x = bitf(d, 11); o0.y = bitf(d, 10); o0.z = bitf(d, 9); o0.w = bitf(d, 8);
        o1.x = bitf(d, 7);  o1.y = bitf(d, 6);  o1.z = bitf(d, 5); o1.w = bitf(d, 4);
        o2.x = bitf(d, 3);  o2.y = bitf(d, 2);  o2.z = bitf(d, 1); o2.w = bitf(d, 0);

        __stcs(&D4[i * 3 + 0], o0);
        __stcs(&D4[i * 3 + 1], o1);
        __stcs(&D4[i * 3 + 2], o2);
        __stcs(&Borrow[i], __uint_as_float((ia < ib) ? 0x3F800000u : 0u));
    }
}

extern "C" void kernel_launch(void* const* d_in, const int* in_sizes, int n_in,
                              void* d_out, int out_size)
{
    const uint4* A4 = (const uint4*)d_in[0];
    const uint4* B4 = (const uint4*)d_in[1];
    const int batch = in_sizes[0] / 12;

    float* out = (float*)d_out;
    uint4* D4 = (uint4*)out;
    float* Borrow = out + (size_t)batch * 12;

    const int threads = 256;
    const int rows_per_block = threads * 2;
    const int blocks = (batch + rows_per_block - 1) / rows_per_block;
    sub12_kernel<<<blocks, threads>>>(A4, B4, D4, Borrow, batch);
}

// round 4
// speedup vs baseline: 1.0117x; 1.0097x over previous
#include <cuda_runtime.h>
#include <stdint.h>

// 12-bit ripple-borrow subtractor on binary (0/1) float spikes.
// Boolean-exact collapse: diffs = bits of ((a-b) & 0xFFF) MSB-first,
// borrow = (a < b). Output: [B*12] diffs row-major, then [B] borrow.
//
// R3: shared-memory staging so every LDG/STG is flat-coalesced
// (4 lines per 128-bit warp access instead of 12 with the 48B row stride).
// Smem row reads (stride 48B) are bank-conflict-free for LDS.128.

#define TPB 256

__device__ __forceinline__ uint32_t pack12(const uint4& w0, const uint4& w1, const uint4& w2) {
    // index 0 = MSB (bit 11) ... index 11 = LSB (bit 0); inputs are 0.0f/1.0f
    uint32_t v = 0;
    v |= (w0.x ? 1u : 0u) << 11;
    v |= (w0.y ? 1u : 0u) << 10;
    v |= (w0.z ? 1u : 0u) << 9;
    v |= (w0.w ? 1u : 0u) << 8;
    v |= (w1.x ? 1u : 0u) << 7;
    v |= (w1.y ? 1u : 0u) << 6;
    v |= (w1.z ? 1u : 0u) << 5;
    v |= (w1.w ? 1u : 0u) << 4;
    v |= (w2.x ? 1u : 0u) << 3;
    v |= (w2.y ? 1u : 0u) << 2;
    v |= (w2.z ? 1u : 0u) << 1;
    v |= (w2.w ? 1u : 0u);
    return v;
}

__device__ __forceinline__ uint32_t bitf(uint32_t d, int bit) {
    return ((d >> bit) & 1u) * 0x3F800000u;  // 1.0f bits or 0
}

__global__ void __launch_bounds__(TPB) sub12_kernel(
    const uint4* __restrict__ A4,
    const uint4* __restrict__ B4,
    uint4* __restrict__ D4,
    float* __restrict__ Borrow,
    int batch)
{
    __shared__ uint4 sA[TPB * 3];
    __shared__ uint4 sB[TPB * 3];

    const int tid = threadIdx.x;
    const int rowBase = blockIdx.x * TPB;
    const size_t vecBase = (size_t)rowBase * 3;

    const int rowsHere = min(TPB, batch - rowBase);
    const int vecsHere = rowsHere * 3;

    // Flat coalesced load of the block's tile (each warp: 512B contiguous).
#pragma unroll
    for (int k = 0; k < 3; k++) {
        const int v = tid + TPB * k;
        if (v < vecsHere) {
            sA[v] = A4[vecBase + v];
            sB[v] = B4[vecBase + v];
        }
    }
    __syncthreads();

    if (tid < rowsHere) {
        const uint4 a0 = sA[tid * 3 + 0];
        const uint4 a1 = sA[tid * 3 + 1];
        const uint4 a2 = sA[tid * 3 + 2];
        const uint4 b0 = sB[tid * 3 + 0];
        const uint4 b1 = sB[tid * 3 + 1];
        const uint4 b2 = sB[tid * 3 + 2];

        const uint32_t ia = pack12(a0, a1, a2);
        const uint32_t ib = pack12(b0, b1, b2);
        const uint32_t d  = (ia - ib) & 0xFFFu;

        uint4 o0, o1, o2;
        o0.x = bitf(d, 11); o0.y = bitf(d, 10); o0.z = bitf(d, 9); o0.w = bitf(d, 8);
        o1.x = bitf(d, 7);  o1.y = bitf(d, 6);  o1.z = bitf(d, 5); o1.w = bitf(d, 4);
        o2.x = bitf(d, 3);  o2.y = bitf(d, 2);  o2.z = bitf(d, 1); o2.w = bitf(d, 0);

        // Each thread overwrites only the slots it alone read — no hazard.
        sA[tid * 3 + 0] = o0;
        sA[tid * 3 + 1] = o1;
        sA[tid * 3 + 2] = o2;

        Borrow[rowBase + tid] = __uint_as_float((ia < ib) ? 0x3F800000u : 0u);
    }
    __syncthreads();

    // Flat coalesced store of the diff tile.
#pragma unroll
    for (int k = 0; k < 3; k++) {
        const int v = tid + TPB * k;
        if (v < vecsHere)
            D4[vecBase + v] = sA[v];
    }
}

extern "C" void kernel_launch(void* const* d_in, const int* in_sizes, int n_in,
                              void* d_out, int out_size)
{
    const uint4* A4 = (const uint4*)d_in[0];
    const uint4* B4 = (const uint4*)d_in[1];
    const int batch = in_sizes[0] / 12;

    float* out = (float*)d_out;
    uint4* D4 = (uint4*)out;
    float* Borrow = out + (size_t)batch * 12;

    const int blocks = (batch + TPB - 1) / TPB;
    sub12_kernel<<<blocks, TPB>>>(A4, B4, D4, Borrow, batch);
}

// round 5
// speedup vs baseline: 1.1901x; 1.1764x over previous
#include <cuda_runtime.h>
#include <stdint.h>

// 12-bit ripple-borrow subtractor on binary (0/1) float spikes.
// Boolean-exact collapse: diffs = bits of ((a-b) & 0xFFF) MSB-first,
// borrow = (a < b). Output: [B*12] diffs row-major, then [B] borrow.
//
// R4: R1 direct-stream structure (best so far, DRAM 82.7%) plus:
//  - __ldcs/__stcs streaming hints (touch-once data, evict-first)
//  - 2 rows/thread BLOCK-STRIDED (rows t and t+TPB): identical per-warp
//    address pattern to R1 for every instruction, 2x loads in flight.

#define TPB 256
#define ROWS_PER_THREAD 2

__device__ __forceinline__ uint32_t pack12(const uint4& w0, const uint4& w1, const uint4& w2) {
    // index 0 = MSB (bit 11) ... index 11 = LSB (bit 0); inputs are 0.0f/1.0f
    uint32_t v = 0;
    v |= (w0.x ? 1u : 0u) << 11;
    v |= (w0.y ? 1u : 0u) << 10;
    v |= (w0.z ? 1u : 0u) << 9;
    v |= (w0.w ? 1u : 0u) << 8;
    v |= (w1.x ? 1u : 0u) << 7;
    v |= (w1.y ? 1u : 0u) << 6;
    v |= (w1.z ? 1u : 0u) << 5;
    v |= (w1.w ? 1u : 0u) << 4;
    v |= (w2.x ? 1u : 0u) << 3;
    v |= (w2.y ? 1u : 0u) << 2;
    v |= (w2.z ? 1u : 0u) << 1;
    v |= (w2.w ? 1u : 0u);
    return v;
}

__device__ __forceinline__ uint32_t bitf(uint32_t d, int bit) {
    return ((d >> bit) & 1u) * 0x3F800000u;  // 1.0f bits or 0
}

__global__ void __launch_bounds__(TPB) sub12_kernel(
    const uint4* __restrict__ A4,
    const uint4* __restrict__ B4,
    uint4* __restrict__ D4,
    float* __restrict__ Borrow,
    int batch)
{
    const int tileBase = blockIdx.x * (TPB * ROWS_PER_THREAD);
    const int tid = threadIdx.x;

    int rows[ROWS_PER_THREAD];
    uint4 a[ROWS_PER_THREAD][3], b[ROWS_PER_THREAD][3];
    bool valid[ROWS_PER_THREAD];

    // Front-batched loads: all 12 LDG.128 issued before any compute.
#pragma unroll
    for (int r = 0; r < ROWS_PER_THREAD; r++) {
        const int i = tileBase + r * TPB + tid;  // block-strided: R1 warp pattern
        rows[r] = i;
        valid[r] = (i < batch);
        if (valid[r]) {
            a[r][0] = __ldcs(&A4[(size_t)i * 3 + 0]);
            a[r][1] = __ldcs(&A4[(size_t)i * 3 + 1]);
            a[r][2] = __ldcs(&A4[(size_t)i * 3 + 2]);
            b[r][0] = __ldcs(&B4[(size_t)i * 3 + 0]);
            b[r][1] = __ldcs(&B4[(size_t)i * 3 + 1]);
            b[r][2] = __ldcs(&B4[(size_t)i * 3 + 2]);
        }
    }

#pragma unroll
    for (int r = 0; r < ROWS_PER_THREAD; r++) {
        if (!valid[r]) continue;
        const int i = rows[r];

        const uint32_t ia = pack12(a[r][0], a[r][1], a[r][2]);
        const uint32_t ib = pack12(b[r][0], b[r][1], b[r][2]);
        const uint32_t d  = (ia - ib) & 0xFFFu;

        uint4 o0, o1, o2;
        o0.x = bitf(d, 11); o0.y = bitf(d, 10); o0.z = bitf(d, 9); o0.w = bitf(d, 8);
        o1.x = bitf(d, 7);  o1.y = bitf(d, 6);  o1.z = bitf(d, 5); o1.w = bitf(d, 4);
        o2.x = bitf(d, 3);  o2.y = bitf(d, 2);  o2.z = bitf(d, 1); o2.w = bitf(d, 0);

        __stcs(&D4[(size_t)i * 3 + 0], o0);
        __stcs(&D4[(size_t)i * 3 + 1], o1);
        __stcs(&D4[(size_t)i * 3 + 2], o2);
        __stcs(&Borrow[i], __uint_as_float((ia < ib) ? 0x3F800000u : 0u));
    }
}

extern "C" void kernel_launch(void* const* d_in, const int* in_sizes, int n_in,
                              void* d_out, int out_size)
{
    const uint4* A4 = (const uint4*)d_in[0];
    const uint4* B4 = (const uint4*)d_in[1];
    const int batch = in_sizes[0] / 12;

    float* out = (float*)d_out;
    uint4* D4 = (uint4*)out;
    float* Borrow = out + (size_t)batch * 12;

    const int rowsPerBlock = TPB * ROWS_PER_THREAD;
    const int blocks = (batch + rowsPerBlock - 1) / rowsPerBlock;
    sub12_kernel<<<blocks, TPB>>>(A4, B4, D4, Borrow, batch);
}